// round 17
// baseline (speedup 1.0000x reference)
#include <cuda_runtime.h>
#include <cstdint>

#define KS     5
#define K2     25
#define DYN    32
#define NB     4
#define NC     64
#define NH     256
#define NW     256
#define HW     (NH*NW)

#define TW     32
#define TH     8
#define PW     4
#define SW     36                 // tile cols w0 .. w0+35 (origin w0, 16B aligned)
#define SH     12                 // rows h0-2 .. h0+9
#define CHK    2                  // channels per chunk
#define F4_CH  (SH*(SW/4))        // 108 float4 per channel
#define F4_CK  (CHK*F4_CH)        // 216 float4 per chunk
#define NSLOT  4                  // ceil(216/64)
#define NTHR   64
#define NCHUNK 32                 // 16 static + 16 dynamic
#define BUFS   8                  // prefetch distance 6, issue-before-wait safe
#define DIST   6

#define SMEM_BYTES (BUFS*F4_CK*16 + NSLOT*NTHR*4 + K2*4)

__device__ __forceinline__ void cp_async16(uint32_t saddr, const float* gaddr, unsigned sz)
{
    asm volatile("cp.async.cg.shared.global [%0], [%1], 16, %2;\n"
                 :: "r"(saddr), "l"(gaddr), "r"(sz) : "memory");
}
__device__ __forceinline__ void cp_commit()
{
    asm volatile("cp.async.commit_group;\n" ::: "memory");
}

__global__ __launch_bounds__(NTHR, 8)
void la_kernel(const float* __restrict__ x,
               const float* __restrict__ kern,
               float* __restrict__ out)
{
    // ===================== EDGE BLOCKS (by == 32): pixels col 0,1 =====================
    if (blockIdx.y == 32) {
        const int tid = threadIdx.x;
        const int b   = blockIdx.z;
        const int R   = blockIdx.x * 32 + (tid >> 1);   // row 0..255
        const int col = tid & 1;                         // 0 or 1
        const float* xb = x + (long)b * NC * HW;

        float sc[K2];
        #pragma unroll
        for (int k = 0; k < K2; ++k) sc[k] = 0.0f;

        for (int ch = DYN; ch < NC; ++ch) {
            const float* cp = xb + ch * HW;
            float4 rowv[KS];
            #pragma unroll
            for (int i = 0; i < KS; ++i) {
                const int gr = R - 2 + i;
                rowv[i] = ((unsigned)gr < NH) ? *(const float4*)(cp + gr * NW)
                                              : make_float4(0.f, 0.f, 0.f, 0.f);
            }
            const float v = (col == 0) ? rowv[2].x : rowv[2].y;
            #pragma unroll
            for (int i = 0; i < KS; ++i) {
                if (col == 0) {
                    sc[i * KS + 2] = fmaf(rowv[i].x, v, sc[i * KS + 2]);
                    sc[i * KS + 3] = fmaf(rowv[i].y, v, sc[i * KS + 3]);
                    sc[i * KS + 4] = fmaf(rowv[i].z, v, sc[i * KS + 4]);
                } else {
                    sc[i * KS + 1] = fmaf(rowv[i].x, v, sc[i * KS + 1]);
                    sc[i * KS + 2] = fmaf(rowv[i].y, v, sc[i * KS + 2]);
                    sc[i * KS + 3] = fmaf(rowv[i].z, v, sc[i * KS + 3]);
                    sc[i * KS + 4] = fmaf(rowv[i].w, v, sc[i * KS + 4]);
                }
            }
        }
        {
            float tmp[K2];
            #pragma unroll
            for (int k = 0; k < K2; ++k) tmp[k] = sc[k] * (__ldg(kern + k) * 0.2f);
            float m2 = tmp[0];
            #pragma unroll
            for (int k = 1; k < K2; ++k) m2 = fmaxf(m2, tmp[k]);
            float sum = 0.0f;
            #pragma unroll
            for (int k = 0; k < K2; ++k) { tmp[k] = __expf(tmp[k] - m2); sum += tmp[k]; }
            const float inv = 1.0f / sum;
            #pragma unroll
            for (int k = 0; k < K2; ++k) sc[k] = tmp[k] * inv;
        }
        for (int ch = 0; ch < DYN; ++ch) {
            const float* cp = xb + ch * HW;
            float acc = 0.0f;
            #pragma unroll
            for (int i = 0; i < KS; ++i) {
                const int gr = R - 2 + i;
                const float4 rv = ((unsigned)gr < NH) ? *(const float4*)(cp + gr * NW)
                                                      : make_float4(0.f, 0.f, 0.f, 0.f);
                if (col == 0) {
                    acc = fmaf(sc[i * KS + 2], rv.x, acc);
                    acc = fmaf(sc[i * KS + 3], rv.y, acc);
                    acc = fmaf(sc[i * KS + 4], rv.z, acc);
                } else {
                    acc = fmaf(sc[i * KS + 1], rv.x, acc);
                    acc = fmaf(sc[i * KS + 2], rv.y, acc);
                    acc = fmaf(sc[i * KS + 3], rv.z, acc);
                    acc = fmaf(sc[i * KS + 4], rv.w, acc);
                }
            }
            out[((long)(b * DYN + ch) * NH + R) * NW + col] = acc;
        }
        return;
    }

    // ===================== MAIN BLOCKS =====================
    extern __shared__ __align__(16) unsigned char dynsm[];
    float4* smbuf = (float4*)dynsm;                             // [BUFS][F4_CK]
    int*    sgoff = (int*)(dynsm + (size_t)BUFS * F4_CK * 16);  // [NSLOT][NTHR]
    float*  skw   = (float*)(sgoff + NSLOT * NTHR);             // [K2]

    const int tid = threadIdx.x;
    const int tx  = tid & 7;                  // 0..7
    const int ty  = tid >> 3;                 // 0..7
    const int w0  = blockIdx.x * TW;
    const int h0  = blockIdx.y * TH;
    const int b   = blockIdx.z;
    const int ph  = h0 + ty;
    const int p0  = w0 + 2 + tx * PW;         // first owned pixel (shifted by +2)

    // fold log2(e)/KS into tap weights -> exp2f softmax
    if (tid < K2) skw[tid] = kern[tid] * (1.4426950408889634f / KS);

    // ---- chunk-invariant fill descriptors; each thread reads only its own rows ----
    #pragma unroll
    for (int s = 0; s < NSLOT; ++s) {
        const int e   = tid + s * NTHR;
        const int ch  = e / F4_CH;
        const int rem = e - ch * F4_CH;
        const int r   = rem / (SW / 4);
        const int j   = rem - r * (SW / 4);
        const int gh  = h0 - 2 + r;
        const int gw0 = w0 + j * 4;
        const bool ok = (e < F4_CK) && ((unsigned)gh < NH) && ((unsigned)gw0 < NW);
        sgoff[s * NTHR + tid] = ok ? (ch * HW + gh * NW + gw0) : -1;
    }

    const float* xb = x + (long)b * NC * HW;

    // chunk -> channel base: 16 static chunks (c=32..63), then 16 dynamic (c=0..31)
    // ---- prologue: issue chunks 0..DIST-1 ----
    #pragma unroll
    for (int pre = 0; pre < DIST; ++pre) {
        const float* g = xb + (32 + CHK * pre) * HW;
        const uint32_t sb = (uint32_t)__cvta_generic_to_shared(&smbuf[(size_t)pre * F4_CK]);
        #pragma unroll
        for (int s = 0; s < NSLOT; ++s) {
            const int e = tid + s * NTHR;
            if (s < NSLOT - 1 || e < F4_CK) {
                const int off = sgoff[s * NTHR + tid];
                cp_async16(sb + (uint32_t)e * 16u, g + (off >= 0 ? off : 0),
                           off >= 0 ? 16u : 0u);
            }
        }
        cp_commit();
    }

    float sc[PW][K2];
    #pragma unroll
    for (int p = 0; p < PW; ++p)
        #pragma unroll
        for (int k = 0; k < K2; ++k) sc[p][k] = 0.0f;

    float inv[PW];

    for (int i = 0; i < NCHUNK; ++i) {
        // 1) issue chunk i+DIST into buffer (i+DIST)%BUFS BEFORE waiting.
        //    That buffer was last read at compute i+DIST-BUFS = i-2, and every
        //    warp passed barrier i-1 after finishing compute i-2 => race-free.
        if (i + DIST < NCHUNK) {
            const int cn = i + DIST;
            const int cb = (cn < 16) ? (32 + CHK * cn) : (CHK * (cn - 16));
            const float* g = xb + cb * HW;
            const uint32_t sb = (uint32_t)__cvta_generic_to_shared(
                &smbuf[(size_t)(cn % BUFS) * F4_CK]);
            #pragma unroll
            for (int s = 0; s < NSLOT; ++s) {
                const int e = tid + s * NTHR;
                if (s < NSLOT - 1 || e < F4_CK) {
                    const int off = sgoff[s * NTHR + tid];
                    cp_async16(sb + (uint32_t)e * 16u, g + (off >= 0 ? off : 0),
                               off >= 0 ? 16u : 0u);
                }
            }
            cp_commit();
        }
        // 2) wait until chunk i complete (exact outstanding count at the tail)
        const int rem = NCHUNK - 1 - i;
        if      (rem >= DIST) { asm volatile("cp.async.wait_group 6;\n" ::: "memory"); }
        else if (rem == 5)    { asm volatile("cp.async.wait_group 5;\n" ::: "memory"); }
        else if (rem == 4)    { asm volatile("cp.async.wait_group 4;\n" ::: "memory"); }
        else if (rem == 3)    { asm volatile("cp.async.wait_group 3;\n" ::: "memory"); }
        else if (rem == 2)    { asm volatile("cp.async.wait_group 2;\n" ::: "memory"); }
        else if (rem == 1)    { asm volatile("cp.async.wait_group 1;\n" ::: "memory"); }
        else                  { asm volatile("cp.async.wait_group 0;\n" ::: "memory"); }
        // 3) barrier: chunk-i data visible to all; all warps done compute i-1
        __syncthreads();

        const float* buf = (const float*)&smbuf[(size_t)(i % BUFS) * F4_CK];

        if (i < 16) {
            // ================= Phase A: scores (scalar FFMA) =================
            #pragma unroll
            for (int cc = 0; cc < CHK; ++cc) {
                const float* chb = buf + cc * (SH * SW) + ty * SW + tx * 4;
                float v[PW];
                {   // row r=2: strip supplies taps AND the 4 center values
                    const float4 A = *(const float4*)(chb + 2 * SW);
                    const float4 B = *(const float4*)(chb + 2 * SW + 4);
                    v[0] = A.z; v[1] = A.w; v[2] = B.x; v[3] = B.y;
                    const float s[8] = {A.x, A.y, A.z, A.w, B.x, B.y, B.z, B.w};
                    #pragma unroll
                    for (int j = 0; j < KS; ++j)
                        #pragma unroll
                        for (int p = 0; p < PW; ++p)
                            sc[p][10 + j] = fmaf(s[j + p], v[p], sc[p][10 + j]);
                }
                #pragma unroll
                for (int rr = 0; rr < 4; ++rr) {
                    const int r = (rr < 2) ? rr : rr + 1;   // 0,1,3,4
                    const float4 A = *(const float4*)(chb + r * SW);
                    const float4 B = *(const float4*)(chb + r * SW + 4);
                    const float s[8] = {A.x, A.y, A.z, A.w, B.x, B.y, B.z, B.w};
                    #pragma unroll
                    for (int j = 0; j < KS; ++j)
                        #pragma unroll
                        for (int p = 0; p < PW; ++p)
                            sc[p][r * KS + j] = fmaf(s[j + p], v[p], sc[p][r * KS + j]);
                }
            }
            if (i == 15) {
                // ========== Phase B: softmax (log2 domain, no max pass) ==========
                // |score * kern * log2e / 5| << 127, so exp2f is overflow-safe
                // without max subtraction (identical math to reference softmax).
                #pragma unroll
                for (int p = 0; p < PW; ++p) {
                    float sum = 0.0f;
                    #pragma unroll
                    for (int k = 0; k < K2; ++k) {
                        const float e = exp2f(sc[p][k] * skw[k]);
                        sc[p][k] = e;
                        sum += e;
                    }
                    inv[p] = 1.0f / sum;
                }
            }
        } else {
            // ================= Phase C: weighted sum (scalar FFMA) =================
            #pragma unroll
            for (int cc = 0; cc < CHK; ++cc) {
                const float* chb = buf + cc * (SH * SW) + ty * SW + tx * 4;
                float acc[PW] = {0.f, 0.f, 0.f, 0.f};
                #pragma unroll
                for (int r = 0; r < KS; ++r) {
                    const float4 A = *(const float4*)(chb + r * SW);
                    const float4 B = *(const float4*)(chb + r * SW + 4);
                    const float s[8] = {A.x, A.y, A.z, A.w, B.x, B.y, B.z, B.w};
                    #pragma unroll
                    for (int j = 0; j < KS; ++j)
                        #pragma unroll
                        for (int p = 0; p < PW; ++p)
                            acc[p] = fmaf(sc[p][r * KS + j], s[j + p], acc[p]);
                }
                const int c = (i - 16) * CHK + cc;
                float* op = &out[(((long)b * DYN + c) * NH + ph) * NW + p0];
                float2 o0 = make_float2(acc[0] * inv[0], acc[1] * inv[1]);
                *(float2*)op = o0;                       // pixels p0, p0+1
                if (p0 + 2 < NW) {                        // masked for last block, tx=7
                    float2 o1 = make_float2(acc[2] * inv[2], acc[3] * inv[3]);
                    *(float2*)(op + 2) = o1;
                }
            }
        }
    }
}

extern "C" void kernel_launch(void* const* d_in, const int* in_sizes, int n_in,
                              void* d_out, int out_size)
{
    const float* x    = (const float*)d_in[0];
    const float* kern = (const float*)d_in[1];
    float* out        = (float*)d_out;
    (void)in_sizes; (void)n_in; (void)out_size;

    static bool attr_set = false;
    if (!attr_set) {
        cudaFuncSetAttribute(la_kernel, cudaFuncAttributeMaxDynamicSharedMemorySize,
                             SMEM_BYTES);
        attr_set = true;
    }

    dim3 grid(NW / TW, NH / TH + 1, NB);   // (8, 33, 4): by==32 -> edge blocks
    dim3 block(NTHR);
    la_kernel<<<grid, block, SMEM_BYTES>>>(x, kern, out);
}